// round 3
// baseline (speedup 1.0000x reference)
#include <cuda_runtime.h>
#include <math.h>

#define N_STEPS 2048
#define N_ARMS 5000
#define HS 10
#define ARMS_PER_BLOCK 8
#define NBLOCKS (N_ARMS / ARMS_PER_BLOCK)  // 625

// ---------------------------------------------------------------------------
// Single fused kernel. Every block redundantly computes the tiny setup
// (MLP -> x0, solve P c = x0, eigen rates) and the 2048-step action table
// directly into shared memory, then streams its 8 arms. All 625 blocks fit
// in one wave, so the prelude runs once in parallel instead of serially
// gating the DRAM-bound stream.
// ---------------------------------------------------------------------------
__global__ void __launch_bounds__(256) fused_kernel(
    const float* __restrict__ target,
    const float4* __restrict__ eps,
    const float* __restrict__ D,
    const float* __restrict__ P,
    const float* __restrict__ W1,
    const float* __restrict__ b1,
    const float* __restrict__ W2,
    const float* __restrict__ b2,
    const float* __restrict__ Wm,
    const float* __restrict__ bm,
    float4* __restrict__ out) {

    __shared__ float s_act[2 * N_STEPS];       // 16 KB action table
    __shared__ float h[256];
    __shared__ float aug[HS][HS + 1];          // [P | x0]
    __shared__ float sP[HS * HS];
    __shared__ float sWm[2 * HS];
    __shared__ float sbm[2];
    __shared__ float sc[HS];
    __shared__ float sll[HS];
    __shared__ float absv[HS];
    __shared__ int pivrow;

    int tid = threadIdx.x;

    // ---- Phase 1: load small tensors + MLP hidden layer -------------------
    {
        float t0 = target[0], t1 = target[1];
        float v = W1[tid * 2] * t0 + W1[tid * 2 + 1] * t1 + b1[tid];
        h[tid] = v > 0.f ? v : 0.f;
    }
    if (tid < HS * HS) {
        float p = P[tid];
        sP[tid] = p;
        aug[tid / HS][tid % HS] = p;
    }
    if (tid < 2 * HS) sWm[tid] = Wm[tid];
    if (tid < 2) sbm[tid] = bm[tid];
    __syncthreads();

    // ---- Phase 2: x0 = W2 @ h + b2 (16 lanes per row, shuffle reduce) -----
    if (tid < HS * 16) {
        int row = tid >> 4;
        int sub = tid & 15;
        const float* w2row = W2 + row * 256;
        float acc = 0.f;
        #pragma unroll
        for (int j = sub; j < 256; j += 16) acc += w2row[j] * h[j];
        #pragma unroll
        for (int s = 8; s > 0; s >>= 1)
            acc += __shfl_down_sync(0xFFFFFFFFu, acc, s, 16);
        if (sub == 0) aug[row][HS] = acc + b2[row];
    }
    __syncthreads();

    // ---- Phase 3: solve P c = x0, Gauss-Jordan, thread=(row,col) cell -----
    {
        int r_ = tid / (HS + 1);
        int c_ = tid % (HS + 1);
        bool cell = tid < HS * (HS + 1);

        for (int k = 0; k < HS; k++) {
            if (tid >= k && tid < HS) absv[tid] = fabsf(aug[tid][k]);
            __syncthreads();
            if (tid == 0) {
                int r = k; float best = absv[k];
                for (int i = k + 1; i < HS; i++) {
                    float m = absv[i];
                    if (m > best) { best = m; r = i; }
                }
                pivrow = r;
            }
            __syncthreads();
            int pr = pivrow;
            // swap + normalize: warp 0 only (lockstep => read-before-write safe)
            if (tid <= HS) {
                float a = aug[k][tid];
                if (pr != k) {
                    float b = aug[pr][tid];
                    aug[pr][tid] = a;
                    a = b;
                }
                float pv = (pr != k) ? aug[pr][k] : a;  // original aug[pr][k] now at row k
                // recompute pivot value consistently: after swap, row k holds old row pr
                // pv must be old aug[pr][k]; for pr==k it's a when tid==k... broadcast below
                aug[k][tid] = a;
            }
            __syncwarp();
            if (tid <= HS) {
                float pv = aug[k][k];
                aug[k][tid] = aug[k][tid] / pv;  // lockstep: all read pv before write
            }
            __syncthreads();
            float f = 0.f, pkc = 0.f, cur = 0.f;
            if (cell && r_ != k) {
                f = aug[r_][k];
                pkc = aug[k][c_];
                cur = aug[r_][c_];
            }
            __syncthreads();
            if (cell && r_ != k) aug[r_][c_] = cur - f * pkc;
            __syncthreads();
        }
    }
    if (tid < HS) {
        sc[tid] = aug[tid][HS];
        sll[tid] = logf(1.0f - 0.01f * expf(D[tid]));
    }
    __syncthreads();

    // ---- Phase 4: action table, parallel-in-time (8 steps per thread) -----
    {
        float bm0 = sbm[0], bm1 = sbm[1];
        #pragma unroll
        for (int k = 0; k < 8; k++) {
            int t = tid + 256 * k;
            float tf = (float)t;
            float w[HS];
            #pragma unroll
            for (int i = 0; i < HS; i++)
                w[i] = sc[i] * __expf(tf * sll[i]);
            float u0 = bm0, u1 = bm1;
            #pragma unroll
            for (int j = 0; j < HS; j++) {
                float xj = 0.f;
                #pragma unroll
                for (int i = 0; i < HS; i++) xj += sP[j * HS + i] * w[i];
                u0 += sWm[j] * xj;
                u1 += sWm[HS + j] * xj;
            }
            s_act[2 * t]     = tanhf(u0);
            s_act[2 * t + 1] = tanhf(u1);
        }
    }
    __syncthreads();

    // ---- Phase 5: stream 8 arms (DRAM-bound) ------------------------------
    const float4* act4 = reinterpret_cast<const float4*>(s_act);
    size_t base = (size_t)blockIdx.x * (ARMS_PER_BLOCK * 1024);
    #pragma unroll
    for (int k = 0; k < 4; k++) {
        float4 a = act4[tid + 256 * k];
        #pragma unroll
        for (int arm = 0; arm < ARMS_PER_BLOCK; arm++) {
            size_t idx = base + (size_t)arm * 1024 + tid + 256 * k;
            float4 e = __ldcs(&eps[idx]);
            float4 o;
            o.x = (a.x + 0.01f * e.x) * 15000.f;
            o.y = (a.y + 0.01f * e.y) * 15000.f;
            o.z = (a.z + 0.01f * e.z) * 15000.f;
            o.w = (a.w + 0.01f * e.w) * 15000.f;
            __stcs(&out[idx], o);
        }
    }
}

extern "C" void kernel_launch(void* const* d_in, const int* in_sizes, int n_in,
                              void* d_out, int out_size) {
    const float* target = (const float*)d_in[0];
    const float* eps    = (const float*)d_in[1];
    const float* D      = (const float*)d_in[2];
    const float* P      = (const float*)d_in[3];
    const float* W1     = (const float*)d_in[4];
    const float* b1     = (const float*)d_in[5];
    const float* W2     = (const float*)d_in[6];
    const float* b2     = (const float*)d_in[7];
    const float* Wm     = (const float*)d_in[8];
    const float* bm     = (const float*)d_in[9];

    fused_kernel<<<NBLOCKS, 256>>>(target, (const float4*)eps, D, P,
                                   W1, b1, W2, b2, Wm, bm, (float4*)d_out);
}